// round 4
// baseline (speedup 1.0000x reference)
#include <cuda_runtime.h>
#include <cuda_bf16.h>
#include <cstdint>
#include <cstddef>

#define DINL __device__ __forceinline__

// ============================== device scratch ==============================
__device__ float g_part[64 * 128];        // encoder layer-1 partial sums
__device__ float g_bg[2];                 // beta, gamma
__device__ float g_sol[8192 * 3];         // SIR states [T][3]
__device__ __align__(128) __nv_bfloat16 g_h2_hi[8192 * 128];
__device__ __align__(128) __nv_bfloat16 g_h2_lo[8192 * 128];
__device__ __align__(128) __nv_bfloat16 g_w3t_hi[8192 * 128];  // W3^T [N][K]
__device__ __align__(128) __nv_bfloat16 g_w3t_lo[8192 * 128];

// ============================== encoder =====================================
__global__ void enc1_kernel(const float* __restrict__ x,
                            const float* __restrict__ w1) {
    int j = threadIdx.x;               // output column 0..127
    int i0 = blockIdx.x * 128;
    float acc = 0.f;
#pragma unroll 4
    for (int i = 0; i < 128; i++)
        acc += x[i0 + i] * w1[(size_t)(i0 + i) * 128 + j];
    g_part[blockIdx.x * 128 + j] = acc;
}

__global__ void enc23_kernel(const float* __restrict__ b1,
                             const float* __restrict__ w2,
                             const float* __restrict__ b2,
                             const float* __restrict__ w3,
                             const float* __restrict__ b3) {
    __shared__ float h1s[128];
    __shared__ float h2s[64];
    int j = threadIdx.x;  // 128 threads
    float acc = b1[j];
    for (int b = 0; b < 64; b++) acc += g_part[b * 128 + j];
    h1s[j] = fmaxf(acc, 0.f);
    __syncthreads();
    if (j < 64) {
        float a2 = b2[j];
#pragma unroll 4
        for (int i = 0; i < 128; i++) a2 += h1s[i] * w2[i * 64 + j];
        h2s[j] = fmaxf(a2, 0.f);
    }
    __syncthreads();
    if (j < 2) {
        float p = b3[j];
        for (int i = 0; i < 64; i++) p += h2s[i] * w3[i * 2 + j];
        g_bg[j] = p;
    }
}

// ============================== ODE (dopri5) ================================
DINL float3 fsir(float3 y, float be, float ga) {
    float b = be * y.x * y.y;
    float g = ga * y.y;
    float3 r; r.x = -b; r.y = b - g; r.z = g;
    return r;
}
DINL float3 mad3(float3 a, float s, float3 b) {
    a.x = fmaf(s, b.x, a.x); a.y = fmaf(s, b.y, a.y); a.z = fmaf(s, b.z, a.z);
    return a;
}
DINL float3 dp5(float3 y, float h, float be, float ga) {
    const float A21 = 0.2f;
    const float A31 = (float)(3.0 / 40.0), A32 = (float)(9.0 / 40.0);
    const float A41 = (float)(44.0 / 45.0), A42 = (float)(-56.0 / 15.0), A43 = (float)(32.0 / 9.0);
    const float A51 = (float)(19372.0 / 6561.0), A52 = (float)(-25360.0 / 2187.0),
                A53 = (float)(64448.0 / 6561.0), A54 = (float)(-212.0 / 729.0);
    const float A61 = (float)(9017.0 / 3168.0), A62 = (float)(-355.0 / 33.0),
                A63 = (float)(46732.0 / 5247.0), A64 = (float)(49.0 / 176.0),
                A65 = (float)(-5103.0 / 18656.0);
    const float B1 = (float)(35.0 / 384.0), B3 = (float)(500.0 / 1113.0),
                B4 = (float)(125.0 / 192.0), B5 = (float)(-2187.0 / 6784.0),
                B6 = (float)(11.0 / 84.0);
    float3 k1 = fsir(y, be, ga);
    float3 yt = mad3(y, h * A21, k1);
    float3 k2 = fsir(yt, be, ga);
    yt = mad3(mad3(y, h * A31, k1), h * A32, k2);
    float3 k3 = fsir(yt, be, ga);
    yt = mad3(mad3(mad3(y, h * A41, k1), h * A42, k2), h * A43, k3);
    float3 k4 = fsir(yt, be, ga);
    yt = mad3(mad3(mad3(mad3(y, h * A51, k1), h * A52, k2), h * A53, k3), h * A54, k4);
    float3 k5 = fsir(yt, be, ga);
    yt = mad3(mad3(mad3(mad3(mad3(y, h * A61, k1), h * A62, k2), h * A63, k3), h * A64, k4),
              h * A65, k5);
    float3 k6 = fsir(yt, be, ga);
    float3 o = mad3(y, h * B1, k1);
    o = mad3(o, h * B3, k3);
    o = mad3(o, h * B4, k4);
    o = mad3(o, h * B5, k5);
    o = mad3(o, h * B6, k6);
    return o;
}

DINL int clampi(int i) { return i < 8191 ? i : 8191; }

__global__ void ode_kernel(const float* __restrict__ t) {
    __shared__ float3 super_s[16];
    __shared__ float3 chunk_s[512];
    const float be = g_bg[0], ga = g_bg[1];
    int tid = threadIdx.x;  // 512 threads

    if (tid == 0) {
        float3 y; y.x = 0.99f; y.y = 0.01f; y.z = 0.f;
        for (int s = 0; s < 16; s++) {
            super_s[s] = y;
            if (s < 15) {
                float h = t[clampi((s + 1) * 512)] - t[s * 512];
                y = dp5(y, h, be, ga);
            }
        }
    }
    __syncthreads();

    if (tid < 16) {
        float3 y = super_s[tid];
        int base = tid * 512;
        for (int c = 0; c < 32; c++) {
            chunk_s[tid * 32 + c] = y;
            float h = t[clampi(base + (c + 1) * 16)] - t[clampi(base + c * 16)];
            y = dp5(y, h, be, ga);
        }
    }
    __syncthreads();

    {
        float3 y = chunk_s[tid];
        int base = tid * 16;
        if (tid == 0) { g_sol[0] = y.x; g_sol[1] = y.y; g_sol[2] = y.z; }
        for (int i = 0; i < 16; i++) {
            int gi = base + i + 1;
            if (gi <= 8191) {
                float h = t[gi] - t[gi - 1];
                y = dp5(y, h, be, ga);
                g_sol[gi * 3 + 0] = y.x;
                g_sol[gi * 3 + 1] = y.y;
                g_sol[gi * 3 + 2] = y.z;
            }
        }
    }
}

// ============================== decoder layers 1-2 ==========================
// 256 blocks x 256 threads; 32 rows per block; w2 staged in SMEM once.
__global__ void __launch_bounds__(256)
dec12_kernel(const float* __restrict__ w1, const float* __restrict__ b1,
             const float* __restrict__ w2, const float* __restrict__ b2) {
    __shared__ float w2s[64 * 128];   // 32 KB
    __shared__ float h1s[32][64];     // 8 KB
    const int tid = threadIdx.x;
    const int row0 = blockIdx.x * 32;

    // stage w2 (8192 floats = 2048 float4)
#pragma unroll
    for (int i = 0; i < 8; i++) {
        int idx = tid + i * 256;
        ((float4*)w2s)[idx] = ((const float4*)w2)[idx];
    }
    // h1 for 32 rows: 2048 entries
#pragma unroll
    for (int i = 0; i < 8; i++) {
        int idx = tid + i * 256;
        int r = idx >> 6, j = idx & 63;
        int row = row0 + r;
        float S = g_sol[row * 3 + 0], I = g_sol[row * 3 + 1], R = g_sol[row * 3 + 2];
        float a = S * w1[j] + I * w1[64 + j] + R * w1[128 + j] + b1[j];
        h1s[r][j] = fmaxf(a, 0.f);
    }
    __syncthreads();

    // h2: thread tile = 2 rows x 8 cols
    const int rp = tid >> 4;          // 0..15 -> rows rp*2, rp*2+1
    const int cg = tid & 15;          // cols cg*8 .. cg*8+7
    const int c0 = cg * 8;
    float acc[2][8];
#pragma unroll
    for (int c = 0; c < 8; c++) { acc[0][c] = b2[c0 + c]; acc[1][c] = acc[0][c]; }
#pragma unroll 8
    for (int i = 0; i < 64; i++) {
        float a0 = h1s[rp * 2 + 0][i];
        float a1 = h1s[rp * 2 + 1][i];
        float4 wA = *(const float4*)&w2s[i * 128 + c0];
        float4 wB = *(const float4*)&w2s[i * 128 + c0 + 4];
        acc[0][0] = fmaf(a0, wA.x, acc[0][0]); acc[0][1] = fmaf(a0, wA.y, acc[0][1]);
        acc[0][2] = fmaf(a0, wA.z, acc[0][2]); acc[0][3] = fmaf(a0, wA.w, acc[0][3]);
        acc[0][4] = fmaf(a0, wB.x, acc[0][4]); acc[0][5] = fmaf(a0, wB.y, acc[0][5]);
        acc[0][6] = fmaf(a0, wB.z, acc[0][6]); acc[0][7] = fmaf(a0, wB.w, acc[0][7]);
        acc[1][0] = fmaf(a1, wA.x, acc[1][0]); acc[1][1] = fmaf(a1, wA.y, acc[1][1]);
        acc[1][2] = fmaf(a1, wA.z, acc[1][2]); acc[1][3] = fmaf(a1, wA.w, acc[1][3]);
        acc[1][4] = fmaf(a1, wB.x, acc[1][4]); acc[1][5] = fmaf(a1, wB.y, acc[1][5]);
        acc[1][6] = fmaf(a1, wB.z, acc[1][6]); acc[1][7] = fmaf(a1, wB.w, acc[1][7]);
    }
#pragma unroll
    for (int rr = 0; rr < 2; rr++) {
        int row = row0 + rp * 2 + rr;
        __nv_bfloat16 hi8[8], lo8[8];
#pragma unroll
        for (int c = 0; c < 8; c++) {
            float v = fmaxf(acc[rr][c], 0.f);
            __nv_bfloat16 hi = __float2bfloat16(v);
            hi8[c] = hi;
            lo8[c] = __float2bfloat16(v - __bfloat162float(hi));
        }
        *(uint4*)&g_h2_hi[row * 128 + c0] = *(uint4*)hi8;
        *(uint4*)&g_h2_lo[row * 128 + c0] = *(uint4*)lo8;
    }
}

// ============================== W3 transpose + split ========================
__global__ void w3prep_kernel(const float* __restrict__ w3) {
    __shared__ float tile[32][33];
    int n0 = blockIdx.x * 32;
    int k0 = blockIdx.y * 32;
    int tx = threadIdx.x & 31;
    int ty = threadIdx.x >> 5;  // 0..7
    for (int r = ty; r < 32; r += 8)
        tile[r][tx] = w3[(size_t)(k0 + r) * 8192 + n0 + tx];
    __syncthreads();
    for (int r = ty; r < 32; r += 8) {
        float v = tile[tx][r];          // (k = k0+tx, n = n0+r)
        __nv_bfloat16 hi = __float2bfloat16(v);
        size_t o = (size_t)(n0 + r) * 128 + k0 + tx;
        g_w3t_hi[o] = hi;
        g_w3t_lo[o] = __float2bfloat16(v - __bfloat162float(hi));
    }
}

// ============================== GEMM (mma.sync bf16, 3-pass hi/lo) ==========
// Persistent-N: 512 CTAs = 64 N-tiles x 8 M-groups; B resident, A double-buffered.
static const int SM_B_HI = 0;
static const int SM_B_LO = 32768;
static const int SM_A0   = 65536;           // stage s at SM_A0 + s*65536; lo at +32768
static const int SM_TOTAL = 196608;         // 192 KB

DINL uint32_t smem_u32(const void* p) { return (uint32_t)__cvta_generic_to_shared(p); }

DINL uint32_t swz(int row, int cc) {
    return (uint32_t)row * 256u + (uint32_t)((cc ^ (row & 7)) << 4);
}

DINL void cp16(uint32_t dst, const void* src) {
    asm volatile("cp.async.cg.shared.global [%0], [%1], 16;" :: "r"(dst), "l"(src));
}

DINL void ldsm_x4(uint32_t& r0, uint32_t& r1, uint32_t& r2, uint32_t& r3, uint32_t addr) {
    asm volatile("ldmatrix.sync.aligned.m8n8.x4.shared.b16 {%0,%1,%2,%3}, [%4];"
                 : "=r"(r0), "=r"(r1), "=r"(r2), "=r"(r3) : "r"(addr));
}

DINL void mma16816(float* d, const uint32_t* a, const uint32_t* b) {
    asm volatile(
        "mma.sync.aligned.m16n8k16.row.col.f32.bf16.bf16.f32 "
        "{%0,%1,%2,%3}, {%4,%5,%6,%7}, {%8,%9}, {%0,%1,%2,%3};"
        : "+f"(d[0]), "+f"(d[1]), "+f"(d[2]), "+f"(d[3])
        : "r"(a[0]), "r"(a[1]), "r"(a[2]), "r"(a[3]), "r"(b[0]), "r"(b[1]));
}

__global__ void __launch_bounds__(256, 1)
gemm_kernel(const float* __restrict__ b3, float* __restrict__ out) {
    extern __shared__ char smem[];
    const uint32_t sb = smem_u32(smem);
    const int tid = threadIdx.x;
    const int lane = tid & 31;
    const int wid = tid >> 5;
    const int wm = wid & 3;     // warp M index (32 rows each)
    const int wn = wid >> 2;    // warp N index (64 cols each)

    const int n_base = (blockIdx.x & 63) * 128;
    const int mg = blockIdx.x >> 6;          // 0..7 -> M-tiles mg*8 .. mg*8+7

    const char* srcBH = (const char*)g_w3t_hi + (size_t)n_base * 256;
    const char* srcBL = (const char*)g_w3t_lo + (size_t)n_base * 256;

    // B resident load (group 0)
#pragma unroll
    for (int i = 0; i < 8; i++) {
        int idx = tid + i * 256;      // 0..2047
        int r = idx >> 4, cc = idx & 15;
        uint32_t d = swz(r, cc);
        size_t s = (size_t)r * 256 + (size_t)cc * 16;
        cp16(sb + SM_B_HI + d, srcBH + s);
        cp16(sb + SM_B_LO + d, srcBL + s);
    }
    asm volatile("cp.async.commit_group;");

    // A stage loader
    auto load_A = [&](int mtile, int stage) {
        const char* srcH = (const char*)g_h2_hi + (size_t)mtile * 128 * 256;
        const char* srcL = (const char*)g_h2_lo + (size_t)mtile * 128 * 256;
        uint32_t base = sb + SM_A0 + stage * 65536;
#pragma unroll
        for (int i = 0; i < 8; i++) {
            int idx = tid + i * 256;
            int r = idx >> 4, cc = idx & 15;
            uint32_t d = swz(r, cc);
            size_t s = (size_t)r * 256 + (size_t)cc * 16;
            cp16(base + d, srcH + s);
            cp16(base + 32768 + d, srcL + s);
        }
        asm volatile("cp.async.commit_group;");
    };

    load_A(mg * 8, 0);  // group 1

    // bias registers (fixed columns for this CTA)
    float bias[8][2];
#pragma unroll
    for (int nt = 0; nt < 8; nt++) {
        int col = n_base + wn * 64 + nt * 8 + (lane & 3) * 2;
        bias[nt][0] = b3[col];
        bias[nt][1] = b3[col + 1];
    }

    // ldmatrix per-lane address components
    const int a_row = wm * 32 + (lane & 15);
    const int a_ccs = (lane >> 4) & 1;
    const int b_row = wn * 64 + ((lane >> 4) & 1) * 8 + (lane & 7);
    const int b_ccs = (lane >> 3) & 1;

    for (int it = 0; it < 8; it++) {
        if (it > 0) __syncthreads();               // stage (it+1)&1 free to overwrite
        if (it + 1 < 8) load_A(mg * 8 + it + 1, (it + 1) & 1);
        if (it + 1 < 8) asm volatile("cp.async.wait_group 1;");
        else            asm volatile("cp.async.wait_group 0;");
        __syncthreads();

        float acc[2][8][4];
#pragma unroll
        for (int mt = 0; mt < 2; mt++)
#pragma unroll
            for (int nt = 0; nt < 8; nt++)
#pragma unroll
                for (int c = 0; c < 4; c++) acc[mt][nt][c] = 0.f;

        const uint32_t aStage = sb + SM_A0 + (it & 1) * 65536;
#pragma unroll
        for (int pass = 0; pass < 3; pass++) {
            const uint32_t aB = aStage + ((pass == 2) ? 32768 : 0);
            const uint32_t bB = sb + ((pass == 1) ? SM_B_LO : SM_B_HI);
#pragma unroll
            for (int ks = 0; ks < 8; ks++) {
                int cc0 = ks * 2;
                uint32_t af[2][4];
#pragma unroll
                for (int mt = 0; mt < 2; mt++)
                    ldsm_x4(af[mt][0], af[mt][1], af[mt][2], af[mt][3],
                            aB + swz(a_row + mt * 16, cc0 + a_ccs));
                uint32_t bf[8][2];
#pragma unroll
                for (int nt2 = 0; nt2 < 4; nt2++) {
                    uint32_t r0, r1, r2, r3;
                    ldsm_x4(r0, r1, r2, r3,
                            bB + swz(b_row + nt2 * 16, cc0 + b_ccs));
                    bf[nt2 * 2][0] = r0; bf[nt2 * 2][1] = r1;
                    bf[nt2 * 2 + 1][0] = r2; bf[nt2 * 2 + 1][1] = r3;
                }
#pragma unroll
                for (int mt = 0; mt < 2; mt++)
#pragma unroll
                    for (int nt = 0; nt < 8; nt++)
                        mma16816(acc[mt][nt], af[mt], bf[nt]);
            }
        }

        // Epilogue: bias + relu, direct float2 stores
        const int m_base = (mg * 8 + it) * 128;
        const int g = lane >> 2;
        const int q = lane & 3;
#pragma unroll
        for (int mt = 0; mt < 2; mt++) {
#pragma unroll
            for (int nt = 0; nt < 8; nt++) {
                int col = n_base + wn * 64 + nt * 8 + q * 2;
#pragma unroll
                for (int h = 0; h < 2; h++) {
                    int row = m_base + wm * 32 + mt * 16 + g + h * 8;
                    float2 v;
                    v.x = fmaxf(acc[mt][nt][h * 2 + 0] + bias[nt][0], 0.f);
                    v.y = fmaxf(acc[mt][nt][h * 2 + 1] + bias[nt][1], 0.f);
                    *(float2*)(out + (size_t)row * 8192 + col) = v;
                }
            }
        }
    }
}

// ============================== launch ======================================
extern "C" void kernel_launch(void* const* d_in, const int* in_sizes, int n_in,
                              void* d_out, int out_size) {
    const float* x      = (const float*)d_in[0];
    const float* t      = (const float*)d_in[1];
    const float* enc_w1 = (const float*)d_in[2];
    const float* enc_b1 = (const float*)d_in[3];
    const float* enc_w2 = (const float*)d_in[4];
    const float* enc_b2 = (const float*)d_in[5];
    const float* enc_w3 = (const float*)d_in[6];
    const float* enc_b3 = (const float*)d_in[7];
    const float* dec_w1 = (const float*)d_in[8];
    const float* dec_b1 = (const float*)d_in[9];
    const float* dec_w2 = (const float*)d_in[10];
    const float* dec_b2 = (const float*)d_in[11];
    const float* dec_w3 = (const float*)d_in[12];
    const float* dec_b3 = (const float*)d_in[13];
    float* out = (float*)d_out;

    {
        dim3 g(256, 4);
        w3prep_kernel<<<g, 256>>>(dec_w3);   // independent: do it first
    }
    enc1_kernel<<<64, 128>>>(x, enc_w1);
    enc23_kernel<<<1, 128>>>(enc_b1, enc_w2, enc_b2, enc_w3, enc_b3);
    ode_kernel<<<1, 512>>>(t);
    dec12_kernel<<<256, 256>>>(dec_w1, dec_b1, dec_w2, dec_b2);
    static bool attr_set = false;
    if (!attr_set) {
        cudaFuncSetAttribute(gemm_kernel, cudaFuncAttributeMaxDynamicSharedMemorySize, SM_TOTAL);
        attr_set = true;
    }
    gemm_kernel<<<512, 256, SM_TOTAL>>>(dec_b3, out);
}

// round 5
// speedup vs baseline: 1.0814x; 1.0814x over previous
#include <cuda_runtime.h>
#include <cuda_bf16.h>
#include <cstdint>
#include <cstddef>

#define DINL __device__ __forceinline__

// ============================== device scratch ==============================
__device__ float g_part[64 * 128];        // encoder layer-1 partial sums
__device__ float g_bg[2];                 // beta, gamma
__device__ float g_sol[8192 * 3];         // SIR states [T][3]
// Pre-swizzled SMEM-image tiles, 64KB per tile (hi image 32KB + lo image 32KB)
__device__ __align__(128) unsigned char g_h2p[64 * 65536];   // A tiles (M)
__device__ __align__(128) unsigned char g_w3tp[64 * 65536];  // B tiles (N)

// swizzled byte offset within one 32KB image: row 0..127, 16B-chunk cc 0..15
DINL uint32_t swz(int row, int cc) {
    return (uint32_t)row * 256u + (uint32_t)((cc ^ (row & 7)) << 4);
}

// ============================== encoder =====================================
__global__ void enc1_kernel(const float* __restrict__ x,
                            const float* __restrict__ w1) {
    int j = threadIdx.x;               // output column 0..127
    int i0 = blockIdx.x * 128;
    float acc = 0.f;
#pragma unroll 4
    for (int i = 0; i < 128; i++)
        acc += x[i0 + i] * w1[(size_t)(i0 + i) * 128 + j];
    g_part[blockIdx.x * 128 + j] = acc;
}

__global__ void enc23_kernel(const float* __restrict__ b1,
                             const float* __restrict__ w2,
                             const float* __restrict__ b2,
                             const float* __restrict__ w3,
                             const float* __restrict__ b3) {
    __shared__ float h1s[128];
    __shared__ float h2s[64];
    int j = threadIdx.x;  // 128 threads
    float acc = b1[j];
    for (int b = 0; b < 64; b++) acc += g_part[b * 128 + j];
    h1s[j] = fmaxf(acc, 0.f);
    __syncthreads();
    if (j < 64) {
        float a2 = b2[j];
#pragma unroll 4
        for (int i = 0; i < 128; i++) a2 += h1s[i] * w2[i * 64 + j];
        h2s[j] = fmaxf(a2, 0.f);
    }
    __syncthreads();
    if (j < 2) {
        float p = b3[j];
        for (int i = 0; i < 64; i++) p += h2s[i] * w3[i * 2 + j];
        g_bg[j] = p;
    }
}

// ============================== ODE (dopri5) ================================
DINL float3 fsir(float3 y, float be, float ga) {
    float b = be * y.x * y.y;
    float g = ga * y.y;
    float3 r; r.x = -b; r.y = b - g; r.z = g;
    return r;
}
DINL float3 mad3(float3 a, float s, float3 b) {
    a.x = fmaf(s, b.x, a.x); a.y = fmaf(s, b.y, a.y); a.z = fmaf(s, b.z, a.z);
    return a;
}
DINL float3 dp5(float3 y, float h, float be, float ga) {
    const float A21 = 0.2f;
    const float A31 = (float)(3.0 / 40.0), A32 = (float)(9.0 / 40.0);
    const float A41 = (float)(44.0 / 45.0), A42 = (float)(-56.0 / 15.0), A43 = (float)(32.0 / 9.0);
    const float A51 = (float)(19372.0 / 6561.0), A52 = (float)(-25360.0 / 2187.0),
                A53 = (float)(64448.0 / 6561.0), A54 = (float)(-212.0 / 729.0);
    const float A61 = (float)(9017.0 / 3168.0), A62 = (float)(-355.0 / 33.0),
                A63 = (float)(46732.0 / 5247.0), A64 = (float)(49.0 / 176.0),
                A65 = (float)(-5103.0 / 18656.0);
    const float B1 = (float)(35.0 / 384.0), B3 = (float)(500.0 / 1113.0),
                B4 = (float)(125.0 / 192.0), B5 = (float)(-2187.0 / 6784.0),
                B6 = (float)(11.0 / 84.0);
    float3 k1 = fsir(y, be, ga);
    float3 yt = mad3(y, h * A21, k1);
    float3 k2 = fsir(yt, be, ga);
    yt = mad3(mad3(y, h * A31, k1), h * A32, k2);
    float3 k3 = fsir(yt, be, ga);
    yt = mad3(mad3(mad3(y, h * A41, k1), h * A42, k2), h * A43, k3);
    float3 k4 = fsir(yt, be, ga);
    yt = mad3(mad3(mad3(mad3(y, h * A51, k1), h * A52, k2), h * A53, k3), h * A54, k4);
    float3 k5 = fsir(yt, be, ga);
    yt = mad3(mad3(mad3(mad3(mad3(y, h * A61, k1), h * A62, k2), h * A63, k3), h * A64, k4),
              h * A65, k5);
    float3 k6 = fsir(yt, be, ga);
    float3 o = mad3(y, h * B1, k1);
    o = mad3(o, h * B3, k3);
    o = mad3(o, h * B4, k4);
    o = mad3(o, h * B5, k5);
    o = mad3(o, h * B6, k6);
    return o;
}

DINL int clampi(int i) { return i < 8191 ? i : 8191; }

__global__ void ode_kernel(const float* __restrict__ t) {
    __shared__ float ts[8192];        // 32 KB: t staged once, coalesced
    __shared__ float3 super_s[16];
    __shared__ float3 chunk_s[512];
    int tid = threadIdx.x;  // 512 threads

    // stage t into smem (2048 float4, 4 per thread)
#pragma unroll
    for (int i = 0; i < 4; i++)
        ((float4*)ts)[tid + i * 512] = ((const float4*)t)[tid + i * 512];
    __syncthreads();

    const float be = g_bg[0], ga = g_bg[1];

    // Level 1: 16 super-spans of 512 intervals; 1 dopri5 step each.
    if (tid == 0) {
        float3 y; y.x = 0.99f; y.y = 0.01f; y.z = 0.f;
        for (int s = 0; s < 16; s++) {
            super_s[s] = y;
            if (s < 15) {
                float h = ts[clampi((s + 1) * 512)] - ts[s * 512];
                y = dp5(y, h, be, ga);
            }
        }
    }
    __syncthreads();

    // Level 2: 16 threads x 32 chunks of 16 intervals each.
    if (tid < 16) {
        float3 y = super_s[tid];
        int base = tid * 512;
        for (int c = 0; c < 32; c++) {
            chunk_s[tid * 32 + c] = y;
            float h = ts[clampi(base + (c + 1) * 16)] - ts[clampi(base + c * 16)];
            y = dp5(y, h, be, ga);
        }
    }
    __syncthreads();

    // Level 3: 512 threads x 16 single-interval steps, writing every state.
    {
        float3 y = chunk_s[tid];
        int base = tid * 16;
        if (tid == 0) { g_sol[0] = y.x; g_sol[1] = y.y; g_sol[2] = y.z; }
        for (int i = 0; i < 16; i++) {
            int gi = base + i + 1;
            if (gi <= 8191) {
                float h = ts[gi] - ts[gi - 1];
                y = dp5(y, h, be, ga);
                g_sol[gi * 3 + 0] = y.x;
                g_sol[gi * 3 + 1] = y.y;
                g_sol[gi * 3 + 2] = y.z;
            }
        }
    }
}

// ============================== decoder layers 1-2 ==========================
// 256 blocks x 256 threads; 32 rows/block; writes pre-swizzled A tile images.
__global__ void __launch_bounds__(256)
dec12_kernel(const float* __restrict__ w1, const float* __restrict__ b1,
             const float* __restrict__ w2, const float* __restrict__ b2) {
    __shared__ float w2s[64 * 128];   // 32 KB
    __shared__ float h1s[32][64];     // 8 KB
    const int tid = threadIdx.x;
    const int row0 = blockIdx.x * 32;

#pragma unroll
    for (int i = 0; i < 8; i++) {
        int idx = tid + i * 256;
        ((float4*)w2s)[idx] = ((const float4*)w2)[idx];
    }
#pragma unroll
    for (int i = 0; i < 8; i++) {
        int idx = tid + i * 256;
        int r = idx >> 6, j = idx & 63;
        int row = row0 + r;
        float S = g_sol[row * 3 + 0], I = g_sol[row * 3 + 1], R = g_sol[row * 3 + 2];
        float a = S * w1[j] + I * w1[64 + j] + R * w1[128 + j] + b1[j];
        h1s[r][j] = fmaxf(a, 0.f);
    }
    __syncthreads();

    const int rp = tid >> 4;          // 0..15 -> rows rp*2, rp*2+1
    const int cg = tid & 15;          // 16B chunk index (cols cg*8..cg*8+7)
    const int c0 = cg * 8;
    float acc[2][8];
#pragma unroll
    for (int c = 0; c < 8; c++) { acc[0][c] = b2[c0 + c]; acc[1][c] = acc[0][c]; }
#pragma unroll 8
    for (int i = 0; i < 64; i++) {
        float a0 = h1s[rp * 2 + 0][i];
        float a1 = h1s[rp * 2 + 1][i];
        float4 wA = *(const float4*)&w2s[i * 128 + c0];
        float4 wB = *(const float4*)&w2s[i * 128 + c0 + 4];
        acc[0][0] = fmaf(a0, wA.x, acc[0][0]); acc[0][1] = fmaf(a0, wA.y, acc[0][1]);
        acc[0][2] = fmaf(a0, wA.z, acc[0][2]); acc[0][3] = fmaf(a0, wA.w, acc[0][3]);
        acc[0][4] = fmaf(a0, wB.x, acc[0][4]); acc[0][5] = fmaf(a0, wB.y, acc[0][5]);
        acc[0][6] = fmaf(a0, wB.z, acc[0][6]); acc[0][7] = fmaf(a0, wB.w, acc[0][7]);
        acc[1][0] = fmaf(a1, wA.x, acc[1][0]); acc[1][1] = fmaf(a1, wA.y, acc[1][1]);
        acc[1][2] = fmaf(a1, wA.z, acc[1][2]); acc[1][3] = fmaf(a1, wA.w, acc[1][3]);
        acc[1][4] = fmaf(a1, wB.x, acc[1][4]); acc[1][5] = fmaf(a1, wB.y, acc[1][5]);
        acc[1][6] = fmaf(a1, wB.z, acc[1][6]); acc[1][7] = fmaf(a1, wB.w, acc[1][7]);
    }
#pragma unroll
    for (int rr = 0; rr < 2; rr++) {
        int row = row0 + rp * 2 + rr;
        int mtile = row >> 7, r = row & 127;
        __nv_bfloat16 hi8[8], lo8[8];
#pragma unroll
        for (int c = 0; c < 8; c++) {
            float v = fmaxf(acc[rr][c], 0.f);
            __nv_bfloat16 hi = __float2bfloat16(v);
            hi8[c] = hi;
            lo8[c] = __float2bfloat16(v - __bfloat162float(hi));
        }
        unsigned char* base = g_h2p + (size_t)mtile * 65536 + swz(r, cg);
        *(uint4*)base = *(uint4*)hi8;
        *(uint4*)(base + 32768) = *(uint4*)lo8;
    }
}

// ============================== W3 transpose + split ========================
// grid (256, 4) x 256 threads: n-block 32 wide, k-block 32 deep.
// Writes pre-swizzled B tile images.
__global__ void w3prep_kernel(const float* __restrict__ w3) {
    __shared__ float tl[32][33];      // [k_local][n_local]
    const int tid = threadIdx.x;
    const int n0 = blockIdx.x * 32;
    const int k0 = blockIdx.y * 32;

#pragma unroll
    for (int i = 0; i < 4; i++) {
        int idx = tid + i * 256;
        int kl = idx >> 5, nl = idx & 31;
        tl[kl][nl] = w3[(size_t)(k0 + kl) * 8192 + n0 + nl];
    }
    __syncthreads();

    int u = tid >> 1;                 // 0..127
    int part = tid & 1;               // 0 = hi, 1 = lo
    int nl = u >> 2;                  // 0..31
    int cq = u & 3;                   // k-chunk within block (0..3)
    __nv_bfloat16 o8[8];
#pragma unroll
    for (int j = 0; j < 8; j++) {
        float v = tl[cq * 8 + j][nl];
        __nv_bfloat16 hi = __float2bfloat16(v);
        o8[j] = part ? __float2bfloat16(v - __bfloat162float(hi)) : hi;
    }
    int ntile = n0 >> 7;
    int r = (n0 & 127) + nl;
    int cc = blockIdx.y * 4 + cq;
    unsigned char* dst = g_w3tp + (size_t)ntile * 65536 + part * 32768 + swz(r, cc);
    *(uint4*)dst = *(uint4*)o8;
}

// ============================== GEMM (mma.sync bf16, 3-pass hi/lo) ==========
// 512 CTAs = 64 N-tiles x 8 M-groups. B resident (1 bulk), A double-buffered
// (1 bulk per M-tile). SMEM: [0,64K) B, [64K,128K) A stage0, [128K,192K) A1.
static const int SM_TOTAL = 196608;

DINL uint32_t smem_u32(const void* p) { return (uint32_t)__cvta_generic_to_shared(p); }

DINL void bulk_g2s(uint32_t dst, const void* src, uint32_t bytes, uint32_t mbar) {
    asm volatile(
        "cp.async.bulk.shared::cta.global.mbarrier::complete_tx::bytes [%0], [%1], %2, [%3];"
        :: "r"(dst), "l"(src), "r"(bytes), "r"(mbar) : "memory");
}
DINL void mbar_init(uint32_t mbar, uint32_t cnt) {
    asm volatile("mbarrier.init.shared.b64 [%0], %1;" :: "r"(mbar), "r"(cnt) : "memory");
}
DINL void mbar_expect(uint32_t mbar, uint32_t bytes) {
    asm volatile("mbarrier.arrive.expect_tx.shared.b64 _, [%0], %1;"
                 :: "r"(mbar), "r"(bytes) : "memory");
}
DINL void mbar_wait(uint32_t mbar, uint32_t parity) {
    asm volatile(
        "{\n\t.reg .pred P;\n\t"
        "WL_%=:\n\t"
        "mbarrier.try_wait.parity.acquire.cta.shared::cta.b64 P, [%0], %1, 0x989680;\n\t"
        "@P bra.uni WD_%=;\n\t"
        "bra.uni WL_%=;\n\t"
        "WD_%=:\n\t}"
        :: "r"(mbar), "r"(parity) : "memory");
}

DINL void ldsm_x4(uint32_t& r0, uint32_t& r1, uint32_t& r2, uint32_t& r3, uint32_t addr) {
    asm volatile("ldmatrix.sync.aligned.m8n8.x4.shared.b16 {%0,%1,%2,%3}, [%4];"
                 : "=r"(r0), "=r"(r1), "=r"(r2), "=r"(r3) : "r"(addr));
}

DINL void mma16816(float* d, const uint32_t* a, const uint32_t* b) {
    asm volatile(
        "mma.sync.aligned.m16n8k16.row.col.f32.bf16.bf16.f32 "
        "{%0,%1,%2,%3}, {%4,%5,%6,%7}, {%8,%9}, {%0,%1,%2,%3};"
        : "+f"(d[0]), "+f"(d[1]), "+f"(d[2]), "+f"(d[3])
        : "r"(a[0]), "r"(a[1]), "r"(a[2]), "r"(a[3]), "r"(b[0]), "r"(b[1]));
}

__global__ void __launch_bounds__(256, 1)
gemm_kernel(const float* __restrict__ b3, float* __restrict__ out) {
    extern __shared__ char smem[];
    __shared__ __align__(8) unsigned long long mbar_s[3];
    const uint32_t sb = smem_u32(smem);
    const uint32_t mb0 = smem_u32(&mbar_s[0]);
    const int tid = threadIdx.x;
    const int lane = tid & 31;
    const int wid = tid >> 5;
    const int wm = wid & 3;     // warp M index (32 rows each)
    const int wn = wid >> 2;    // warp N index (64 cols each)

    const int ntile = blockIdx.x & 63;
    const int n_base = ntile * 128;
    const int mg = blockIdx.x >> 6;          // 0..7 -> M-tiles mg*8 .. mg*8+7

    if (tid == 0) {
        mbar_init(mb0 + 0, 1);
        mbar_init(mb0 + 8, 1);
        mbar_init(mb0 + 16, 1);
    }
    __syncthreads();

    if (tid == 0) {
        mbar_expect(mb0 + 16, 65536);
        bulk_g2s(sb, g_w3tp + (size_t)ntile * 65536, 65536, mb0 + 16);
        mbar_expect(mb0 + 0, 65536);
        bulk_g2s(sb + 65536, g_h2p + (size_t)(mg * 8) * 65536, 65536, mb0 + 0);
    }

    // bias registers (source-fragment columns for this warp)
    float bias[8][2];
#pragma unroll
    for (int nt = 0; nt < 8; nt++) {
        int col = n_base + wn * 64 + nt * 8 + (lane & 3) * 2;
        bias[nt][0] = b3[col];
        bias[nt][1] = b3[col + 1];
    }

    // ldmatrix per-lane address components
    const int a_row = wm * 32 + (lane & 15);
    const int a_ccs = (lane >> 4) & 1;
    const int b_row = wn * 64 + ((lane >> 4) & 1) * 8 + (lane & 7);
    const int b_ccs = (lane >> 3) & 1;

    const int g = lane >> 2;
    const int qt = lane & 3;
    const int src0 = (lane & ~3) | ((lane & 1) << 1);
    const int src1 = src0 | 1;
    const bool bsel = (lane & 2) != 0;

    for (int it = 0; it < 8; it++) {
        // issue next A tile into the other stage (free since iter it-1 synced)
        if (tid == 0 && it + 1 < 8) {
            uint32_t m = mb0 + ((it + 1) & 1) * 8;
            mbar_expect(m, 65536);
            bulk_g2s(sb + 65536 + ((it + 1) & 1) * 65536,
                     g_h2p + (size_t)(mg * 8 + it + 1) * 65536, 65536, m);
        }
        mbar_wait(mb0 + (it & 1) * 8, (it >> 1) & 1);
        if (it == 0) mbar_wait(mb0 + 16, 0);

        float acc[2][8][4];
#pragma unroll
        for (int mt = 0; mt < 2; mt++)
#pragma unroll
            for (int nt = 0; nt < 8; nt++)
#pragma unroll
                for (int c = 0; c < 4; c++) acc[mt][nt][c] = 0.f;

        const uint32_t aStage = sb + 65536 + (it & 1) * 65536;
#pragma unroll
        for (int pass = 0; pass < 3; pass++) {
            const uint32_t aB = aStage + ((pass == 2) ? 32768 : 0);
            const uint32_t bB = sb + ((pass == 1) ? 32768 : 0);
#pragma unroll
            for (int ks = 0; ks < 8; ks++) {
                int cc0 = ks * 2;
                uint32_t af[2][4];
#pragma unroll
                for (int mt = 0; mt < 2; mt++)
                    ldsm_x4(af[mt][0], af[mt][1], af[mt][2], af[mt][3],
                            aB + swz(a_row + mt * 16, cc0 + a_ccs));
                uint32_t bf[8][2];
#pragma unroll
                for (int nt2 = 0; nt2 < 4; nt2++) {
                    uint32_t r0, r1, r2, r3;
                    ldsm_x4(r0, r1, r2, r3,
                            bB + swz(b_row + nt2 * 16, cc0 + b_ccs));
                    bf[nt2 * 2][0] = r0; bf[nt2 * 2][1] = r1;
                    bf[nt2 * 2 + 1][0] = r2; bf[nt2 * 2 + 1][1] = r3;
                }
#pragma unroll
                for (int mt = 0; mt < 2; mt++)
#pragma unroll
                    for (int nt = 0; nt < 8; nt++)
                        mma16816(acc[mt][nt], af[mt], bf[nt]);
            }
        }
        __syncthreads();   // stage consumed; next bulk may overwrite

        // Epilogue: bias + relu, shfl repack -> STG.128 (4 consecutive cols/lane)
        const int m_base = (mg * 8 + it) * 128;
#pragma unroll
        for (int mt = 0; mt < 2; mt++) {
#pragma unroll
            for (int s = 0; s < 4; s++) {
#pragma unroll
                for (int h = 0; h < 2; h++) {
                    float a0x = fmaxf(acc[mt][2 * s + 0][h * 2 + 0] + bias[2 * s + 0][0], 0.f);
                    float a0y = fmaxf(acc[mt][2 * s + 0][h * 2 + 1] + bias[2 * s + 0][1], 0.f);
                    float a1x = fmaxf(acc[mt][2 * s + 1][h * 2 + 0] + bias[2 * s + 1][0], 0.f);
                    float a1y = fmaxf(acc[mt][2 * s + 1][h * 2 + 1] + bias[2 * s + 1][1], 0.f);
                    float f0x0 = __shfl_sync(0xffffffffu, a0x, src0);
                    float f0y0 = __shfl_sync(0xffffffffu, a0y, src0);
                    float f0x1 = __shfl_sync(0xffffffffu, a0x, src1);
                    float f0y1 = __shfl_sync(0xffffffffu, a0y, src1);
                    float f1x0 = __shfl_sync(0xffffffffu, a1x, src0);
                    float f1y0 = __shfl_sync(0xffffffffu, a1y, src0);
                    float f1x1 = __shfl_sync(0xffffffffu, a1x, src1);
                    float f1y1 = __shfl_sync(0xffffffffu, a1y, src1);
                    float4 v;
                    v.x = bsel ? f1x0 : f0x0;
                    v.y = bsel ? f1y0 : f0y0;
                    v.z = bsel ? f1x1 : f0x1;
                    v.w = bsel ? f1y1 : f0y1;
                    int row = m_base + wm * 32 + mt * 16 + g + h * 8;
                    int col = n_base + wn * 64 + s * 16 + qt * 4;
                    *(float4*)(out + (size_t)row * 8192 + col) = v;
                }
            }
        }
    }
}

// ============================== launch ======================================
extern "C" void kernel_launch(void* const* d_in, const int* in_sizes, int n_in,
                              void* d_out, int out_size) {
    const float* x      = (const float*)d_in[0];
    const float* t      = (const float*)d_in[1];
    const float* enc_w1 = (const float*)d_in[2];
    const float* enc_b1 = (const float*)d_in[3];
    const float* enc_w2 = (const float*)d_in[4];
    const float* enc_b2 = (const float*)d_in[5];
    const float* enc_w3 = (const float*)d_in[6];
    const float* enc_b3 = (const float*)d_in[7];
    const float* dec_w1 = (const float*)d_in[8];
    const float* dec_b1 = (const float*)d_in[9];
    const float* dec_w2 = (const float*)d_in[10];
    const float* dec_b2 = (const float*)d_in[11];
    const float* dec_w3 = (const float*)d_in[12];
    const float* dec_b3 = (const float*)d_in[13];
    float* out = (float*)d_out;

    {
        dim3 g(256, 4);
        w3prep_kernel<<<g, 256>>>(dec_w3);   // independent of encoder/ODE
    }
    enc1_kernel<<<64, 128>>>(x, enc_w1);
    enc23_kernel<<<1, 128>>>(enc_b1, enc_w2, enc_b2, enc_w3, enc_b3);
    ode_kernel<<<1, 512>>>(t);
    dec12_kernel<<<256, 256>>>(dec_w1, dec_b1, dec_w2, dec_b2);
    cudaFuncSetAttribute(gemm_kernel, cudaFuncAttributeMaxDynamicSharedMemorySize, SM_TOTAL);
    gemm_kernel<<<512, 256, SM_TOTAL>>>(dec_b3, out);
}